// round 6
// baseline (speedup 1.0000x reference)
#include <cuda_runtime.h>
#include <cstdint>
#include <cfloat>

// Sparsemax (d = 4096), max-seeded Michelot with candidate compaction:
//   M = max(row); thr0 = M - 1  (tau* >= M-1, support subset of {x > thr0})
//   Pass 1 doubles as compaction (survivors -> smem) + Michelot iter 1.
//   Remaining iterations: ALL warps run the loop redundantly over the
//   ~60-element compacted set (identical deterministic result), so there is
//   no serial single-warp tail and no third barrier.
//   out = max(x - tau, 0).
// Row resident in registers (256 thr x 4 float4); HBM touched once each way.

#define ROW_D     4096
#define THREADS   256
#define NW        (THREADS / 32)
#define V4_PER_T  4

__global__ __launch_bounds__(THREADS, 6)
void sparsemax_kernel(const float* __restrict__ x, float* __restrict__ out)
{
    __shared__ float  s_max[NW];
    __shared__ float2 s_sc[NW];
    __shared__ int    s_n;
    __shared__ float  s_buf[ROW_D];   // worst case: all elements survive

    const size_t row_base = (size_t)blockIdx.x * ROW_D;
    const float4* __restrict__ xr  = reinterpret_cast<const float4*>(x + row_base);
    float4*       __restrict__ orr = reinterpret_cast<float4*>(out + row_base);

    const int tid = threadIdx.x;
    const int wid = tid >> 5;
    const int lid = tid & 31;

    // ---- load row into registers (front-batched, MLP=4) ----
    float4 v4[V4_PER_T];
#pragma unroll
    for (int i = 0; i < V4_PER_T; ++i)
        v4[i] = xr[tid + i * THREADS];

    // ---- pass 1a: row max ----
    float m = -FLT_MAX;
#pragma unroll
    for (int i = 0; i < V4_PER_T; ++i) {
        const float4 q = v4[i];
        m = fmaxf(m, fmaxf(fmaxf(q.x, q.y), fmaxf(q.z, q.w)));
    }
#pragma unroll
    for (int o = 16; o > 0; o >>= 1)
        m = fmaxf(m, __shfl_xor_sync(0xFFFFFFFFu, m, o));
    if (lid == 0) s_max[wid] = m;
    if (tid == 0) s_n = 0;
    __syncthreads();                                   // barrier 1

    float M = s_max[0];
#pragma unroll
    for (int w = 1; w < NW; ++w) M = fmaxf(M, s_max[w]);
    const float thr0 = M - 1.0f;

    // ---- pass 1b: compact survivors + accumulate (sum, count) ----
    float s = 0.0f, c = 0.0f;
    int   myc = 0;
#pragma unroll
    for (int i = 0; i < V4_PER_T; ++i) {
        const float4 q = v4[i];
        if (q.x > thr0) { s += q.x; c += 1.0f; ++myc; }
        if (q.y > thr0) { s += q.y; c += 1.0f; ++myc; }
        if (q.z > thr0) { s += q.z; c += 1.0f; ++myc; }
        if (q.w > thr0) { s += q.w; c += 1.0f; ++myc; }
    }
    if (myc > 0) {
        int pos = atomicAdd(&s_n, myc);
#pragma unroll
        for (int i = 0; i < V4_PER_T; ++i) {
            const float4 q = v4[i];
            if (q.x > thr0) s_buf[pos++] = q.x;
            if (q.y > thr0) s_buf[pos++] = q.y;
            if (q.z > thr0) s_buf[pos++] = q.z;
            if (q.w > thr0) s_buf[pos++] = q.w;
        }
    }
#pragma unroll
    for (int o = 16; o > 0; o >>= 1) {
        s += __shfl_xor_sync(0xFFFFFFFFu, s, o);
        c += __shfl_xor_sync(0xFFFFFFFFu, c, o);
    }
    if (lid == 0) s_sc[wid] = make_float2(s, c);
    __syncthreads();                                   // barrier 2 (last one)

    // ---- ALL warps: redundant Michelot iterations over the compacted set ----
    // Same data + same FP order in every warp -> bit-identical tau; no
    // broadcast, no barrier, no idle warps.
    float S = 0.0f, C = 0.0f;
#pragma unroll
    for (int w = 0; w < NW; ++w) { S += s_sc[w].x; C += s_sc[w].y; }
    const int n = s_n;

    float tau  = (S - 1.0f) / C;       // iteration 1 (set = all survivors)
    int   prev = (int)C;

    for (int iter = 0; iter < 32; ++iter) {
        float ls = 0.0f, lc = 0.0f;
        for (int j = lid; j < n; j += 32) {            // stride-1 LDS, conflict-free
            const float v = s_buf[j];
            if (v > tau) { ls += v; lc += 1.0f; }
        }
#pragma unroll
        for (int o = 16; o > 0; o >>= 1) {
            ls += __shfl_xor_sync(0xFFFFFFFFu, ls, o);
            lc += __shfl_xor_sync(0xFFFFFFFFu, lc, o);
        }
        const int cnt = (int)lc;        // >= 1: M always > tau (tau <= tau* < M)
        const float ntau = (ls - 1.0f) / lc;
        tau = ntau;
        if (cnt == prev) break;         // set unchanged -> tau exact
        prev = cnt;
    }

    // ---- epilogue: out = max(x - tau, 0) ----
#pragma unroll
    for (int i = 0; i < V4_PER_T; ++i) {
        const float4 q = v4[i];
        float4 o;
        o.x = fmaxf(q.x - tau, 0.0f);
        o.y = fmaxf(q.y - tau, 0.0f);
        o.z = fmaxf(q.z - tau, 0.0f);
        o.w = fmaxf(q.w - tau, 0.0f);
        orr[tid + i * THREADS] = o;
    }
}

extern "C" void kernel_launch(void* const* d_in, const int* in_sizes, int n_in,
                              void* d_out, int out_size)
{
    const float* x   = (const float*)d_in[0];
    float*       out = (float*)d_out;
    const int n_rows = in_sizes[0] / ROW_D;   // 16384
    sparsemax_kernel<<<n_rows, THREADS>>>(x, out);
}